// round 15
// baseline (speedup 1.0000x reference)
#include <cuda_runtime.h>
#include <math.h>
#include <stdint.h>

#define N_ROWS 16384
#define DIM 256
#define DT_F 0.01f

// row tiling: 112 rows/block, grid 147 (146*112=16352, last block 32 valid rows)
#define BROWS 112
#define GRID_N 147

typedef unsigned long long u64;

#define FMA2(acc, a2, b2) \
    asm("fma.rn.f32x2 %0, %1, %2, %3;" : "=l"(acc) : "l"(a2), "l"(b2), "l"(acc))
#define FMA2O(d, a2, b2, c2) \
    asm("fma.rn.f32x2 %0, %1, %2, %3;" : "=l"(d) : "l"(a2), "l"(b2), "l"(c2))

__device__ __forceinline__ u64 dup2(float a) {
    u64 r; uint32_t au = __float_as_uint(a);
    asm("mov.b64 %0, {%1, %1};" : "=l"(r) : "r"(au));
    return r;
}
__device__ __forceinline__ u64 pack2(float lo, float hi) {
    u64 r;
    asm("mov.b64 %0, {%1, %2};" : "=l"(r)
        : "r"(__float_as_uint(lo)), "r"(__float_as_uint(hi)));
    return r;
}
__device__ __forceinline__ void unpk(u64 x, float& lo, float& hi) {
    uint32_t l, h;
    asm("mov.b64 {%0, %1}, %2;" : "=r"(l), "=r"(h) : "l"(x));
    lo = __uint_as_float(l); hi = __uint_as_float(h);
}
__device__ __forceinline__ u64 relu2(u64 x) {
    float lo, hi; unpk(x, lo, hi);
    return pack2(fmaxf(lo, 0.f), fmaxf(hi, 0.f));
}

// ---------------------------------------------------------------------------
// Fully fused kernel: 112 rows per block, 448 threads.
// Phase A (MLP): 14 warps x 8 rows each, packed f32x2 FFMA; Hs doubles as
//   the stage-1 input tile; xi handed to phase B via smem.
// Phase B (scan): 4 threads/row, f32x2-packed hidden units, ytile aliases Hs.
// ---------------------------------------------------------------------------
#define BK   16
#define RPW  8      // rows per warp in MLP phase (14 warps x 8 = 112)
#define OFF_WS (BROWS * DIM)
#define OFF_XI (BROWS * DIM + 2 * BK * DIM)
#define FUSED_SMEM ((BROWS * DIM + 2 * BK * DIM + BROWS) * 4)

extern __shared__ float smem[];

__global__ __launch_bounds__(448, 1)
void fused_kernel(const float* __restrict__ data,
                  const float* __restrict__ omega,
                  const float* __restrict__ eps,
                  const float* __restrict__ W1,  const float* __restrict__ b1,
                  const float* __restrict__ W2,  const float* __restrict__ b2,
                  const float* __restrict__ Wm1, const float* __restrict__ bm1,
                  const float* __restrict__ Wm2, const float* __restrict__ bm2,
                  const float* __restrict__ Wl1, const float* __restrict__ bl1,
                  const float* __restrict__ Wl2, const float* __restrict__ bl2,
                  const float* __restrict__ Wa1, const float* __restrict__ ba1,
                  const float* __restrict__ Wa2, const float* __restrict__ ba2,
                  float* __restrict__ out)
{
    float* Hs   = smem;                      // 112 x 256 (data -> activations)
    float* Ws   = smem + OFF_WS;             // 2 x (16 x 256)
    float* xi_s = smem + OFF_XI;             // 112 xi values

    const int tid = threadIdx.x;
    const int tc  = tid & 31;                // lane -> column pairs tc*2 + 64p
    const int wd  = tid >> 5;                // warp id 0..13 -> rows wd*8..+7
    const int row0 = blockIdx.x * BROWS;

    // W-tile prefetch done by threads 0..255 (4 float4 each -> 1024 float4)
    const bool pf_on = (tid < 256);
    const int pf_k[4] = { tid >> 6, (tid + 256) >> 6, (tid + 512) >> 6, (tid + 768) >> 6 };
    const int pf_c = (tid & 63) * 4;

    u64 acc[RPW][4];
    float4 wreg[4];

    // preload data tile into Hs: 112 x 64 float4 = 7168 float4, 448 thr x 16
    #pragma unroll
    for (int u = 0; u < 16; u++) {
        int idx = tid + u * 448;             // float4 idx 0..7167
        int r = idx >> 6;
        int c4 = (idx & 63) * 4;
        int gr = min(row0 + r, N_ROWS - 1);
        *(float4*)&Hs[r * DIM + c4] =
            *(const float4*)&data[(size_t)gr * DIM + c4];
    }
    __syncthreads();

    #define GEMM_TILE(Wt, k0)                                                   \
        _Pragma("unroll")                                                       \
        for (int kq = 0; kq < BK / 2; kq++) {                                   \
            u64 bq0[4], bq1[4];                                                 \
            _Pragma("unroll")                                                   \
            for (int p = 0; p < 4; p++) {                                       \
                bq0[p] = *(const u64*)&(Wt)[(2*kq)     * DIM + tc * 2 + 64 * p];\
                bq1[p] = *(const u64*)&(Wt)[(2*kq + 1) * DIM + tc * 2 + 64 * p];\
            }                                                                   \
            _Pragma("unroll")                                                   \
            for (int i = 0; i < RPW; i++) {                                     \
                u64 a01 = *(const u64*)&Hs[(wd * RPW + i) * DIM + (k0) + 2*kq]; \
                float alo, ahi; unpk(a01, alo, ahi);                            \
                u64 a2l = dup2(alo), a2h = dup2(ahi);                           \
                _Pragma("unroll")                                               \
                for (int p = 0; p < 4; p++) {                                   \
                    FMA2(acc[i][p], a2l, bq0[p]);                               \
                    FMA2(acc[i][p], a2h, bq1[p]);                               \
                }                                                               \
            }                                                                   \
        }

    // =======================================================================
    // Stage 1: Hs = relu([data|omega] @ W1 + b1)
    // =======================================================================
    #pragma unroll
    for (int i = 0; i < RPW; i++)
        #pragma unroll
        for (int p = 0; p < 4; p++) acc[i][p] = 0ull;

    if (pf_on) {
        #pragma unroll
        for (int u = 0; u < 4; u++)
            wreg[u] = *(const float4*)&W1[(size_t)pf_k[u] * DIM + pf_c];
        #pragma unroll
        for (int u = 0; u < 4; u++)
            *(float4*)&Ws[pf_k[u] * DIM + pf_c] = wreg[u];
        #pragma unroll
        for (int u = 0; u < 4; u++)
            wreg[u] = *(const float4*)&W1[(size_t)(BK + pf_k[u]) * DIM + pf_c];
    }

    for (int t = 0; t < 16; t++) {
        const int buf = t & 1;
        if (t > 0 && pf_on) {
            #pragma unroll
            for (int u = 0; u < 4; u++)
                *(float4*)&Ws[buf * BK * DIM + pf_k[u] * DIM + pf_c] = wreg[u];
        }
        __syncthreads();
        if (t + 1 < 16 && pf_on) {
            #pragma unroll
            for (int u = 0; u < 4; u++)
                wreg[u] = *(const float4*)&W1[(size_t)((t + 1) * BK + pf_k[u]) * DIM + pf_c];
        }
        const float* Wt = &Ws[buf * BK * DIM];
        GEMM_TILE(Wt, t * BK)
    }
    __syncthreads();
    // epilogue: omega column (k=256), bias, relu -> Hs (own rows only)
    {
        float aom[RPW];
        #pragma unroll
        for (int i = 0; i < RPW; i++)
            aom[i] = omega[min(row0 + wd * RPW + i, N_ROWS - 1)];
        #pragma unroll
        for (int p = 0; p < 4; p++) {
            int c = tc * 2 + 64 * p;
            u64 bom = *(const u64*)&W1[(size_t)256 * DIM + c];
            float2 bb = *(const float2*)&b1[c];
            #pragma unroll
            for (int i = 0; i < RPW; i++) {
                u64 s;
                FMA2O(s, dup2(aom[i]), bom, acc[i][p]);
                float lo, hi; unpk(s, lo, hi);
                float2 o;
                o.x = fmaxf(lo + bb.x, 0.f);
                o.y = fmaxf(hi + bb.y, 0.f);
                *(float2*)&Hs[(wd * RPW + i) * DIM + c] = o;
            }
        }
    }
    __syncthreads();

    // =======================================================================
    // Stage 2: Hs = relu(Hs @ W2 + b2)
    // =======================================================================
    #pragma unroll
    for (int i = 0; i < RPW; i++)
        #pragma unroll
        for (int p = 0; p < 4; p++) acc[i][p] = 0ull;

    if (pf_on) {
        #pragma unroll
        for (int u = 0; u < 4; u++)
            wreg[u] = *(const float4*)&W2[(size_t)pf_k[u] * DIM + pf_c];
        #pragma unroll
        for (int u = 0; u < 4; u++)
            *(float4*)&Ws[pf_k[u] * DIM + pf_c] = wreg[u];
        #pragma unroll
        for (int u = 0; u < 4; u++)
            wreg[u] = *(const float4*)&W2[(size_t)(BK + pf_k[u]) * DIM + pf_c];
    }

    for (int t = 0; t < 16; t++) {
        const int buf = t & 1;
        if (t > 0 && pf_on) {
            #pragma unroll
            for (int u = 0; u < 4; u++)
                *(float4*)&Ws[buf * BK * DIM + pf_k[u] * DIM + pf_c] = wreg[u];
        }
        __syncthreads();
        if (t + 1 < 16 && pf_on) {
            #pragma unroll
            for (int u = 0; u < 4; u++)
                wreg[u] = *(const float4*)&W2[(size_t)((t + 1) * BK + pf_k[u]) * DIM + pf_c];
        }
        const float* Wt = &Ws[buf * BK * DIM];
        GEMM_TILE(Wt, t * BK)
    }
    __syncthreads();
    {
        #pragma unroll
        for (int p = 0; p < 4; p++) {
            int c = tc * 2 + 64 * p;
            float2 bb = *(const float2*)&b2[c];
            #pragma unroll
            for (int i = 0; i < RPW; i++) {
                float lo, hi; unpk(acc[i][p], lo, hi);
                float2 o;
                o.x = fmaxf(lo + bb.x, 0.f);
                o.y = fmaxf(hi + bb.y, 0.f);
                *(float2*)&Hs[(wd * RPW + i) * DIM + c] = o;
            }
        }
    }
    __syncthreads();

    // =======================================================================
    // Stage 3: Hs = relu(Hs @ [Wm1|Wl1] + [bm1|bl1])
    // =======================================================================
    #pragma unroll
    for (int i = 0; i < RPW; i++)
        #pragma unroll
        for (int p = 0; p < 4; p++) acc[i][p] = 0ull;

    const int s3c = (pf_c < 128) ? pf_c : pf_c - 128;
    const float* S3 = (pf_c < 128) ? Wm1 : Wl1;

    if (pf_on) {
        #pragma unroll
        for (int u = 0; u < 4; u++)
            wreg[u] = *(const float4*)&S3[(size_t)pf_k[u] * 128 + s3c];
        #pragma unroll
        for (int u = 0; u < 4; u++)
            *(float4*)&Ws[pf_k[u] * DIM + pf_c] = wreg[u];
        #pragma unroll
        for (int u = 0; u < 4; u++)
            wreg[u] = *(const float4*)&S3[(size_t)(BK + pf_k[u]) * 128 + s3c];
    }

    for (int t = 0; t < 16; t++) {
        const int buf = t & 1;
        if (t > 0 && pf_on) {
            #pragma unroll
            for (int u = 0; u < 4; u++)
                *(float4*)&Ws[buf * BK * DIM + pf_k[u] * DIM + pf_c] = wreg[u];
        }
        __syncthreads();
        if (t + 1 < 16 && pf_on) {
            #pragma unroll
            for (int u = 0; u < 4; u++)
                wreg[u] = *(const float4*)&S3[(size_t)((t + 1) * BK + pf_k[u]) * 128 + s3c];
        }
        const float* Wt = &Ws[buf * BK * DIM];
        GEMM_TILE(Wt, t * BK)
    }
    __syncthreads();
    {
        #pragma unroll
        for (int p = 0; p < 4; p++) {
            int c = tc * 2 + 64 * p;
            float2 bb;
            if (c < 128) bb = *(const float2*)&bm1[c];
            else         bb = *(const float2*)&bl1[c - 128];
            #pragma unroll
            for (int i = 0; i < RPW; i++) {
                float lo, hi; unpk(acc[i][p], lo, hi);
                float2 o;
                o.x = fmaxf(lo + bb.x, 0.f);
                o.y = fmaxf(hi + bb.y, 0.f);
                *(float2*)&Hs[(wd * RPW + i) * DIM + c] = o;
            }
        }
    }
    __syncthreads();

    // ===================== Stage 4: head reductions ========================
    {
        const float bm2v = bm2[0];
        const float bl2v = bl2[0];
        #pragma unroll 1
        for (int q = 0; q < RPW; q++) {
            int r = wd * RPW + q;
            float s1 = 0.f, s2 = 0.f;
            #pragma unroll
            for (int m = 0; m < 4; m++) {
                int h = tc + 32 * m;
                s1 = fmaf(Hs[r * DIM + h],       __ldg(&Wm2[h]), s1);
                s2 = fmaf(Hs[r * DIM + 128 + h], __ldg(&Wl2[h]), s2);
            }
            #pragma unroll
            for (int o = 16; o > 0; o >>= 1) {
                s1 += __shfl_xor_sync(0xffffffffu, s1, o);
                s2 += __shfl_xor_sync(0xffffffffu, s2, o);
            }
            int gr = row0 + r;
            if (tc == 0) {
                float pm = s1 + bm2v;
                float lv = s2 + bl2v;
                float xm = fmaxf(pm, 0.f) + log1pf(expf(-fabsf(pm)));
                float xi = xm + expf(0.5f * lv) * ((gr < N_ROWS) ? eps[gr] : 0.f);
                xi = fminf(fmaxf(xi, 0.f), 1.f);
                xi_s[r] = xi;
                if (gr < N_ROWS) {
                    out[gr]          = xm;   // xi_mean
                    out[N_ROWS + gr] = lv;   // xi_lnvar
                }
            }
        }
    }
    __syncthreads();

    // =======================================================================
    // Phase B: scan. 4 threads/row, 16 units each as 8 f32x2 pairs.
    // ytile aliases the (now free) Hs region.
    // =======================================================================
    {
        float (*ytile)[33] = (float (*)[33])smem;

        const int l4  = tid & 3;
        const int r   = tid >> 2;                 // local row 0..111
        const int row = row0 + r;
        const int rowc = min(row, N_ROWS - 1);

        u64 w2[8], v2[8], c2[8];
        const float om = omega[rowc];
        #pragma unroll
        for (int q = 0; q < 8; q++) {
            int j = l4 * 16 + 2 * q;
            float2 wf = *(const float2*)&Wa1[64 + j];
            float2 vf = *(const float2*)&Wa2[j];
            w2[q] = pack2(wf.x, wf.y);
            v2[q] = pack2(vf.x, vf.y);
            c2[q] = pack2(fmaf(om, Wa1[j],     ba1[j]),
                          fmaf(om, Wa1[j + 1], ba1[j + 1]));
        }
        const float b2v = ba2[0];

        float y  = data[(size_t)rowc * DIM];
        float vv = 0.f;
        const float xi = xi_s[r];
        const float dm = expf(-xi * DT_F);
        float f = 1.f;

        float* __restrict__ xout = out + 2 * N_ROWS;
        __syncthreads();   // ensure all warps read xi_s & Hs is reusable

        for (int t = 0; t < 256; t++) {
            if (l4 == 0) ytile[r][t & 31] = f * y;

            u64 y2 = dup2(y);
            u64 acc2a = 0ull, acc2b = 0ull;
            #pragma unroll
            for (int q = 0; q < 8; q += 2) {
                u64 h0, h1;
                FMA2O(h0, y2, w2[q],     c2[q]);
                FMA2O(h1, y2, w2[q + 1], c2[q + 1]);
                FMA2(acc2a, relu2(h0), v2[q]);
                FMA2(acc2b, relu2(h1), v2[q + 1]);
            }
            float alo, ahi, blo, bhi;
            unpk(acc2a, alo, ahi);
            unpk(acc2b, blo, bhi);
            float acc = (alo + ahi) + (blo + bhi);
            acc += __shfl_xor_sync(0xffffffffu, acc, 1);
            acc += __shfl_xor_sync(0xffffffffu, acc, 2);
            acc += b2v;

            float ynew = fmaf(DT_F, vv, y);
            vv = fmaf(DT_F, acc, vv);
            y  = ynew;
            f *= dm;

            if ((t & 31) == 31) {
                __syncthreads();
                int tb = t - 31;
                #pragma unroll
                for (int i = 0; i < 8; i++) {
                    int idx = i * 448 + tid;      // 0..3583 over 112x32 tile
                    int rr  = idx >> 5;
                    int cc  = idx & 31;
                    int grow = row0 + rr;
                    if (grow < N_ROWS)
                        xout[(size_t)grow * DIM + tb + cc] = ytile[rr][cc];
                }
                __syncthreads();
            }
        }
    }
}

// ---------------------------------------------------------------------------
extern "C" void kernel_launch(void* const* d_in, const int* in_sizes, int n_in,
                              void* d_out, int out_size)
{
    const float* data = (const float*)d_in[0];
    const float* omega= (const float*)d_in[1];
    const float* eps  = (const float*)d_in[2];
    const float* W1   = (const float*)d_in[3];  const float* b1  = (const float*)d_in[4];
    const float* W2   = (const float*)d_in[5];  const float* b2  = (const float*)d_in[6];
    const float* Wm1  = (const float*)d_in[7];  const float* bm1 = (const float*)d_in[8];
    const float* Wm2  = (const float*)d_in[9];  const float* bm2 = (const float*)d_in[10];
    const float* Wl1  = (const float*)d_in[11]; const float* bl1 = (const float*)d_in[12];
    const float* Wl2  = (const float*)d_in[13]; const float* bl2 = (const float*)d_in[14];
    const float* Wa1  = (const float*)d_in[15]; const float* ba1 = (const float*)d_in[16];
    const float* Wa2  = (const float*)d_in[17]; const float* ba2 = (const float*)d_in[18];
    float* out = (float*)d_out;

    cudaFuncSetAttribute(fused_kernel,
                         cudaFuncAttributeMaxDynamicSharedMemorySize, FUSED_SMEM);

    fused_kernel<<<GRID_N, 448, FUSED_SMEM>>>(
        data, omega, eps, W1, b1, W2, b2,
        Wm1, bm1, Wm2, bm2, Wl1, bl1, Wl2, bl2,
        Wa1, ba1, Wa2, ba2, out);
}

// round 17
// speedup vs baseline: 1.0447x; 1.0447x over previous
#include <cuda_runtime.h>
#include <math.h>
#include <float.h>
#include <stdint.h>

#define N_ROWS 16384
#define DIM 256
#define DT_F 0.01f

#define BROWS 112
#define GRID_N 147

__device__ float g_xi[N_ROWS];

typedef unsigned long long u64;

#define FMA2(acc, a2, b2) \
    asm("fma.rn.f32x2 %0, %1, %2, %3;" : "=l"(acc) : "l"(a2), "l"(b2), "l"(acc))
#define FMA2O(d, a2, b2, c2) \
    asm("fma.rn.f32x2 %0, %1, %2, %3;" : "=l"(d) : "l"(a2), "l"(b2), "l"(c2))

__device__ __forceinline__ u64 dup2(float a) {
    u64 r; uint32_t au = __float_as_uint(a);
    asm("mov.b64 %0, {%1, %1};" : "=l"(r) : "r"(au));
    return r;
}
__device__ __forceinline__ void unpk(u64 x, float& lo, float& hi) {
    uint32_t l, h;
    asm("mov.b64 {%0, %1}, %2;" : "=r"(l), "=r"(h) : "l"(x));
    lo = __uint_as_float(l); hi = __uint_as_float(h);
}

// ---------------------------------------------------------------------------
// MLP kernel: EXACT R13 config (256 threads, 8 warps x 14 rows, f32x2 FFMA).
// ---------------------------------------------------------------------------
#define BK   16
#define RPW  14
#define OFF_WS (BROWS * DIM)
#define MLP_SMEM ((BROWS * DIM + 2 * BK * DIM) * 4)

extern __shared__ float smem[];

__global__ __launch_bounds__(256, 1)
void mlp_kernel(const float* __restrict__ data,
                const float* __restrict__ omega,
                const float* __restrict__ eps,
                const float* __restrict__ W1,  const float* __restrict__ b1,
                const float* __restrict__ W2,  const float* __restrict__ b2,
                const float* __restrict__ Wm1, const float* __restrict__ bm1,
                const float* __restrict__ Wm2, const float* __restrict__ bm2,
                const float* __restrict__ Wl1, const float* __restrict__ bl1,
                const float* __restrict__ Wl2, const float* __restrict__ bl2,
                float* __restrict__ out)
{
    float* Hs = smem;
    float* Ws = smem + OFF_WS;

    const int tid = threadIdx.x;
    const int tc  = tid & 31;
    const int wd  = tid >> 5;
    const int row0 = blockIdx.x * BROWS;

    const int pf_k[4] = { tid >> 6, (tid + 256) >> 6, (tid + 512) >> 6, (tid + 768) >> 6 };
    const int pf_c = (tid & 63) * 4;

    u64 acc[RPW][4];
    float4 wreg[4];

    #pragma unroll
    for (int u = 0; u < 28; u++) {
        int idx = tid + u * 256;
        int r = idx >> 6;
        int c4 = (idx & 63) * 4;
        int gr = min(row0 + r, N_ROWS - 1);
        *(float4*)&Hs[r * DIM + c4] =
            *(const float4*)&data[(size_t)gr * DIM + c4];
    }
    __syncthreads();

    #define GEMM_TILE(Wt, k0)                                                   \
        _Pragma("unroll")                                                       \
        for (int kq = 0; kq < BK / 2; kq++) {                                   \
            u64 bq0[4], bq1[4];                                                 \
            _Pragma("unroll")                                                   \
            for (int p = 0; p < 4; p++) {                                       \
                bq0[p] = *(const u64*)&(Wt)[(2*kq)     * DIM + tc * 2 + 64 * p];\
                bq1[p] = *(const u64*)&(Wt)[(2*kq + 1) * DIM + tc * 2 + 64 * p];\
            }                                                                   \
            _Pragma("unroll")                                                   \
            for (int i = 0; i < RPW; i++) {                                     \
                u64 a01 = *(const u64*)&Hs[(wd * RPW + i) * DIM + (k0) + 2*kq]; \
                float alo, ahi; unpk(a01, alo, ahi);                            \
                u64 a2l = dup2(alo), a2h = dup2(ahi);                           \
                _Pragma("unroll")                                               \
                for (int p = 0; p < 4; p++) {                                   \
                    FMA2(acc[i][p], a2l, bq0[p]);                               \
                    FMA2(acc[i][p], a2h, bq1[p]);                               \
                }                                                               \
            }                                                                   \
        }

    // Stage 1
    #pragma unroll
    for (int i = 0; i < RPW; i++)
        #pragma unroll
        for (int p = 0; p < 4; p++) acc[i][p] = 0ull;

    #pragma unroll
    for (int u = 0; u < 4; u++)
        wreg[u] = *(const float4*)&W1[(size_t)pf_k[u] * DIM + pf_c];
    #pragma unroll
    for (int u = 0; u < 4; u++)
        *(float4*)&Ws[pf_k[u] * DIM + pf_c] = wreg[u];
    #pragma unroll
    for (int u = 0; u < 4; u++)
        wreg[u] = *(const float4*)&W1[(size_t)(BK + pf_k[u]) * DIM + pf_c];

    for (int t = 0; t < 16; t++) {
        const int buf = t & 1;
        if (t > 0) {
            #pragma unroll
            for (int u = 0; u < 4; u++)
                *(float4*)&Ws[buf * BK * DIM + pf_k[u] * DIM + pf_c] = wreg[u];
        }
        __syncthreads();
        if (t + 1 < 16) {
            #pragma unroll
            for (int u = 0; u < 4; u++)
                wreg[u] = *(const float4*)&W1[(size_t)((t + 1) * BK + pf_k[u]) * DIM + pf_c];
        }
        const float* Wt = &Ws[buf * BK * DIM];
        GEMM_TILE(Wt, t * BK)
    }
    __syncthreads();
    {
        float aom[RPW];
        #pragma unroll
        for (int i = 0; i < RPW; i++)
            aom[i] = omega[min(row0 + wd * RPW + i, N_ROWS - 1)];
        #pragma unroll
        for (int p = 0; p < 4; p++) {
            int c = tc * 2 + 64 * p;
            u64 bom = *(const u64*)&W1[(size_t)256 * DIM + c];
            float2 bb = *(const float2*)&b1[c];
            #pragma unroll
            for (int i = 0; i < RPW; i++) {
                u64 s;
                FMA2O(s, dup2(aom[i]), bom, acc[i][p]);
                float lo, hi; unpk(s, lo, hi);
                float2 o;
                o.x = fmaxf(lo + bb.x, 0.f);
                o.y = fmaxf(hi + bb.y, 0.f);
                *(float2*)&Hs[(wd * RPW + i) * DIM + c] = o;
            }
        }
    }
    __syncthreads();

    // Stage 2
    #pragma unroll
    for (int i = 0; i < RPW; i++)
        #pragma unroll
        for (int p = 0; p < 4; p++) acc[i][p] = 0ull;

    #pragma unroll
    for (int u = 0; u < 4; u++)
        wreg[u] = *(const float4*)&W2[(size_t)pf_k[u] * DIM + pf_c];
    #pragma unroll
    for (int u = 0; u < 4; u++)
        *(float4*)&Ws[pf_k[u] * DIM + pf_c] = wreg[u];
    #pragma unroll
    for (int u = 0; u < 4; u++)
        wreg[u] = *(const float4*)&W2[(size_t)(BK + pf_k[u]) * DIM + pf_c];

    for (int t = 0; t < 16; t++) {
        const int buf = t & 1;
        if (t > 0) {
            #pragma unroll
            for (int u = 0; u < 4; u++)
                *(float4*)&Ws[buf * BK * DIM + pf_k[u] * DIM + pf_c] = wreg[u];
        }
        __syncthreads();
        if (t + 1 < 16) {
            #pragma unroll
            for (int u = 0; u < 4; u++)
                wreg[u] = *(const float4*)&W2[(size_t)((t + 1) * BK + pf_k[u]) * DIM + pf_c];
        }
        const float* Wt = &Ws[buf * BK * DIM];
        GEMM_TILE(Wt, t * BK)
    }
    __syncthreads();
    {
        #pragma unroll
        for (int p = 0; p < 4; p++) {
            int c = tc * 2 + 64 * p;
            float2 bb = *(const float2*)&b2[c];
            #pragma unroll
            for (int i = 0; i < RPW; i++) {
                float lo, hi; unpk(acc[i][p], lo, hi);
                float2 o;
                o.x = fmaxf(lo + bb.x, 0.f);
                o.y = fmaxf(hi + bb.y, 0.f);
                *(float2*)&Hs[(wd * RPW + i) * DIM + c] = o;
            }
        }
    }
    __syncthreads();

    // Stage 3
    #pragma unroll
    for (int i = 0; i < RPW; i++)
        #pragma unroll
        for (int p = 0; p < 4; p++) acc[i][p] = 0ull;

    const int s3c = (pf_c < 128) ? pf_c : pf_c - 128;
    const float* S3 = (pf_c < 128) ? Wm1 : Wl1;

    #pragma unroll
    for (int u = 0; u < 4; u++)
        wreg[u] = *(const float4*)&S3[(size_t)pf_k[u] * 128 + s3c];
    #pragma unroll
    for (int u = 0; u < 4; u++)
        *(float4*)&Ws[pf_k[u] * DIM + pf_c] = wreg[u];
    #pragma unroll
    for (int u = 0; u < 4; u++)
        wreg[u] = *(const float4*)&S3[(size_t)(BK + pf_k[u]) * 128 + s3c];

    for (int t = 0; t < 16; t++) {
        const int buf = t & 1;
        if (t > 0) {
            #pragma unroll
            for (int u = 0; u < 4; u++)
                *(float4*)&Ws[buf * BK * DIM + pf_k[u] * DIM + pf_c] = wreg[u];
        }
        __syncthreads();
        if (t + 1 < 16) {
            #pragma unroll
            for (int u = 0; u < 4; u++)
                wreg[u] = *(const float4*)&S3[(size_t)((t + 1) * BK + pf_k[u]) * 128 + s3c];
        }
        const float* Wt = &Ws[buf * BK * DIM];
        GEMM_TILE(Wt, t * BK)
    }
    __syncthreads();
    {
        #pragma unroll
        for (int p = 0; p < 4; p++) {
            int c = tc * 2 + 64 * p;
            float2 bb;
            if (c < 128) bb = *(const float2*)&bm1[c];
            else         bb = *(const float2*)&bl1[c - 128];
            #pragma unroll
            for (int i = 0; i < RPW; i++) {
                float lo, hi; unpk(acc[i][p], lo, hi);
                float2 o;
                o.x = fmaxf(lo + bb.x, 0.f);
                o.y = fmaxf(hi + bb.y, 0.f);
                *(float2*)&Hs[(wd * RPW + i) * DIM + c] = o;
            }
        }
    }
    __syncthreads();

    // Stage 4: heads
    const float bm2v = bm2[0];
    const float bl2v = bl2[0];
    #pragma unroll 1
    for (int q = 0; q < RPW; q++) {
        int r = wd * RPW + q;
        float s1 = 0.f, s2 = 0.f;
        #pragma unroll
        for (int m = 0; m < 4; m++) {
            int h = tc + 32 * m;
            s1 = fmaf(Hs[r * DIM + h],       __ldg(&Wm2[h]), s1);
            s2 = fmaf(Hs[r * DIM + 128 + h], __ldg(&Wl2[h]), s2);
        }
        #pragma unroll
        for (int o = 16; o > 0; o >>= 1) {
            s1 += __shfl_xor_sync(0xffffffffu, s1, o);
            s2 += __shfl_xor_sync(0xffffffffu, s2, o);
        }
        int gr = row0 + r;
        if (tc == 0 && gr < N_ROWS) {
            float pm = s1 + bm2v;
            float lv = s2 + bl2v;
            float xm = fmaxf(pm, 0.f) + log1pf(expf(-fabsf(pm)));
            float xi = xm + expf(0.5f * lv) * eps[gr];
            xi = fminf(fmaxf(xi, 0.f), 1.f);
            out[gr]            = xm;
            out[N_ROWS + gr]   = lv;
            g_xi[gr]           = xi;
        }
    }
}

// ---------------------------------------------------------------------------
// Scan kernel v5: piecewise-linear segment tracking.
// acc(y) = A_k*y + B_k on segment k; breakpoints sorted once per row.
// Setup: 4 threads/row rank-sort 64 breakpoints. Loop: 1 thread/row,
// 3 FMA + 2 compares per step; segment walk only on crossing.
// ---------------------------------------------------------------------------
#define SW 68   // padded table width (entries 0..65 used for bp table)
#define OFF_BPU 0
#define OFF_BPT (BROWS * SW)
#define OFF_DA  (2 * BROWS * SW)
#define OFF_DB  (3 * BROWS * SW)
#define OFF_YT  (4 * BROWS * SW)
#define SCAN_SMEM ((4 * BROWS * SW + BROWS * 33) * 4)

__global__ __launch_bounds__(448, 1)
void scan_kernel(const float* __restrict__ data,
                 const float* __restrict__ omega,
                 const float* __restrict__ Wa1, const float* __restrict__ ba1,
                 const float* __restrict__ Wa2, const float* __restrict__ ba2,
                 float* __restrict__ out)
{
    float* bp_u = smem + OFF_BPU;            // [112][68] unsorted breakpoints
    float* bp_t = smem + OFF_BPT;            // [112][68] sorted, 0..65 used
    float* dA_t = smem + OFF_DA;             // [112][68] event deltas (0..63)
    float* dB_t = smem + OFF_DB;
    float (*ytile)[33] = (float (*)[33])(smem + OFF_YT);

    const int tid = threadIdx.x;
    const int l4  = tid & 3;
    const int r   = tid >> 2;                // local row 0..111
    const int row = blockIdx.x * BROWS + r;
    const int rowc = min(row, N_ROWS - 1);

    // ---- setup: this thread's 16 units ----
    float w[16], v[16], cc[16];
    const float om = omega[rowc];
    float Ab = 0.f, Bb = 0.f;                // baseline at y -> -inf
    #pragma unroll
    for (int i = 0; i < 16; i++) {
        int j = l4 * 16 + i;
        w[i]  = Wa1[64 + j];
        v[i]  = Wa2[j];
        cc[i] = fmaf(om, Wa1[j], ba1[j]);
        float bp = (w[i] != 0.f) ? (-cc[i] / w[i]) : FLT_MAX;
        bp_u[r * SW + j] = bp;
        if (w[i] < 0.f)      { Ab += v[i] * w[i]; Bb += v[i] * cc[i]; }
        else if (w[i] == 0.f && cc[i] > 0.f) Bb += v[i] * cc[i];
    }
    __syncthreads();

    // ---- rank-sort: each thread ranks its 16 bps against all 64 ----
    #pragma unroll 1
    for (int i = 0; i < 16; i++) {
        int j = l4 * 16 + i;
        float bpj = bp_u[r * SW + j];
        int rank = 0;
        #pragma unroll 8
        for (int q = 0; q < 64; q++) {
            float bq = bp_u[r * SW + q];
            rank += (bq < bpj) || (bq == bpj && q < j);
        }
        float s  = (w[i] > 0.f) ? 1.f : -1.f;
        float da = (w[i] == 0.f) ? 0.f : s * v[i] * w[i];
        float db = (w[i] == 0.f) ? 0.f : s * v[i] * cc[i];
        bp_t[r * SW + rank + 1] = bpj;
        dA_t[r * SW + rank] = da;
        dB_t[r * SW + rank] = db;
    }
    if (l4 == 0) {
        bp_t[r * SW + 0]  = -FLT_MAX;
        bp_t[r * SW + 65] =  FLT_MAX;
    }
    // combine baseline over the 4 sub-threads of this row
    Ab += __shfl_xor_sync(0xffffffffu, Ab, 1);
    Ab += __shfl_xor_sync(0xffffffffu, Ab, 2);
    Bb += __shfl_xor_sync(0xffffffffu, Bb, 1);
    Bb += __shfl_xor_sync(0xffffffffu, Bb, 2);
    __syncthreads();

    // ---- main loop (one thread per row) ----
    float y = 0.f, vv = 0.f, f = 1.f, dm = 1.f;
    float A = 0.f, B = 0.f, bp_lo = 0.f, bp_hi = 0.f;
    int k = 0;
    if (l4 == 0) {
        y  = data[(size_t)rowc * DIM];
        const float xi = g_xi[rowc];
        dm = expf(-xi * DT_F);
        A = Ab;
        B = Bb + ba2[0];
        // init walk to y's segment
        bp_hi = bp_t[r * SW + 1];
        while (y >= bp_hi) {
            A += dA_t[r * SW + k];
            B += dB_t[r * SW + k];
            k++;
            bp_hi = bp_t[r * SW + k + 1];
        }
        bp_lo = bp_t[r * SW + k];
    }

    float* __restrict__ xout = out + 2 * N_ROWS;

    for (int t = 0; t < 256; t++) {
        if (l4 == 0) {
            ytile[r][t & 31] = f * y;

            float acc  = fmaf(A, y, B);        // A*y + B  (incl. b2)
            float ynew = fmaf(DT_F, vv, y);
            vv = fmaf(DT_F, acc, vv);
            y  = ynew;
            f *= dm;

            if (y >= bp_hi) {
                do {
                    A += dA_t[r * SW + k];
                    B += dB_t[r * SW + k];
                    k++;
                    bp_hi = bp_t[r * SW + k + 1];
                } while (y >= bp_hi);
                bp_lo = bp_t[r * SW + k];
            } else if (y < bp_lo) {
                do {
                    k--;
                    A -= dA_t[r * SW + k];
                    B -= dB_t[r * SW + k];
                    bp_lo = bp_t[r * SW + k];
                } while (y < bp_lo);
                bp_hi = bp_t[r * SW + k + 1];
            }
        }
        if ((t & 31) == 31) {
            __syncthreads();
            int tb = t - 31;
            #pragma unroll
            for (int i = 0; i < 8; i++) {
                int idx = i * 448 + tid;      // 0..3583 over 112x32 tile
                int rr  = idx >> 5;
                int ccx = idx & 31;
                int grow = blockIdx.x * BROWS + rr;
                if (grow < N_ROWS)
                    xout[(size_t)grow * DIM + tb + ccx] = ytile[rr][ccx];
            }
            __syncthreads();
        }
    }
}

// ---------------------------------------------------------------------------
extern "C" void kernel_launch(void* const* d_in, const int* in_sizes, int n_in,
                              void* d_out, int out_size)
{
    const float* data = (const float*)d_in[0];
    const float* omega= (const float*)d_in[1];
    const float* eps  = (const float*)d_in[2];
    const float* W1   = (const float*)d_in[3];  const float* b1  = (const float*)d_in[4];
    const float* W2   = (const float*)d_in[5];  const float* b2  = (const float*)d_in[6];
    const float* Wm1  = (const float*)d_in[7];  const float* bm1 = (const float*)d_in[8];
    const float* Wm2  = (const float*)d_in[9];  const float* bm2 = (const float*)d_in[10];
    const float* Wl1  = (const float*)d_in[11]; const float* bl1 = (const float*)d_in[12];
    const float* Wl2  = (const float*)d_in[13]; const float* bl2 = (const float*)d_in[14];
    const float* Wa1  = (const float*)d_in[15]; const float* ba1 = (const float*)d_in[16];
    const float* Wa2  = (const float*)d_in[17]; const float* ba2 = (const float*)d_in[18];
    float* out = (float*)d_out;

    cudaFuncSetAttribute(mlp_kernel,
                         cudaFuncAttributeMaxDynamicSharedMemorySize, MLP_SMEM);
    cudaFuncSetAttribute(scan_kernel,
                         cudaFuncAttributeMaxDynamicSharedMemorySize, SCAN_SMEM);

    mlp_kernel<<<GRID_N, 256, MLP_SMEM>>>(
        data, omega, eps, W1, b1, W2, b2,
        Wm1, bm1, Wm2, bm2, Wl1, bl1, Wl2, bl2, out);

    scan_kernel<<<GRID_N, 448, SCAN_SMEM>>>(data, omega, Wa1, ba1, Wa2, ba2, out);
}